// round 1
// baseline (speedup 1.0000x reference)
#include <cuda_runtime.h>
#include <math.h>

#define H 256
#define A_TOT 262144
#define A_MAP 131072
#define NH 4

// ---------------- scratch (device globals; no allocation allowed) ----------------
__device__ float g_keys[(size_t)A_TOT * H];          // 256 MB
__device__ float g_scores[NH * A_TOT];               // 4 MB
__device__ float g_logits[A_TOT];                    // 1 MB
__device__ float g_W1aT_map[H * H];
__device__ float g_W1aT_sch[H * H];
__device__ float g_W1bT_map[H * H];
__device__ float g_W1bT_sch[H * H];
__device__ float g_W2T_map[H * H];
__device__ float g_W2T_sch[H * H];
__device__ float g_qpu_contrib[64 * H];
__device__ float g_time_contrib[1000 * H];
__device__ float g_gsum[H];
__device__ float g_U[NH * H];
__device__ float g_c[NH];
__device__ float g_attn_out[H];
__device__ float g_cvec[NH * H];
__device__ float g_expsum[NH];
__device__ unsigned g_smax[NH];
__device__ unsigned g_lmax;
__device__ float g_lsum;

// ordered-uint encoding for fp32 atomic max
__device__ __forceinline__ unsigned f2ord(float f) {
    unsigned u = __float_as_uint(f);
    return (u & 0x80000000u) ? ~u : (u | 0x80000000u);
}
__device__ __forceinline__ float ord2f(unsigned u) {
    u = (u & 0x80000000u) ? (u ^ 0x80000000u) : ~u;
    return __uint_as_float(u);
}

// ---------------- init (reset accumulators every launch; graph-replay safe) ------
__global__ void k_init() {
    int t = threadIdx.x;
    if (t < H) g_gsum[t] = 0.0f;
    if (t < NH * H) g_cvec[t] = 0.0f;
    if (t < NH) { g_expsum[t] = 0.0f; g_smax[t] = 0x007FFFFFu; /* f2ord(-inf) */ }
    if (t == 0) { g_lsum = 0.0f; g_lmax = 0x007FFFFFu; }
}

// ---------------- transpose the weight matrices we stream as B operands ----------
__global__ void k_transpose(const float* __restrict__ mapW1, const float* __restrict__ schW1,
                            const float* __restrict__ mapW2, const float* __restrict__ schW2) {
    __shared__ float s[32][33];
    const float* src; float* dst; int ld, off;
    switch (blockIdx.y) {
        case 0: src = mapW1; ld = 512; off = 0;   dst = g_W1aT_map; break;
        case 1: src = mapW1; ld = 512; off = 256; dst = g_W1bT_map; break;
        case 2: src = schW1; ld = 512; off = 0;   dst = g_W1aT_sch; break;
        case 3: src = schW1; ld = 512; off = 256; dst = g_W1bT_sch; break;
        case 4: src = mapW2; ld = 256; off = 0;   dst = g_W2T_map;  break;
        default: src = schW2; ld = 256; off = 0;  dst = g_W2T_sch;  break;
    }
    int k0 = (blockIdx.x & 7) * 32;
    int n0 = (blockIdx.x >> 3) * 32;
    int tx = threadIdx.x, ty = threadIdx.y;  // 32 x 8
#pragma unroll
    for (int i = 0; i < 32; i += 8)
        s[ty + i][tx] = src[(size_t)(n0 + ty + i) * ld + off + k0 + tx];
    __syncthreads();
#pragma unroll
    for (int i = 0; i < 32; i += 8)
        dst[(size_t)(k0 + ty + i) * H + n0 + tx] = s[tx][ty + i];
}

// ---------------- g = mean(all_embeddings) ---------------------------------------
__global__ void k_mean(const float* __restrict__ all_emb) {
    int t = threadIdx.x;
    size_t base = (size_t)blockIdx.x * 256;
    float s = 0.0f;
    for (int r = 0; r < 256; r++) s += all_emb[(base + r) * H + t];
    atomicAdd(&g_gsum[t], s);
}

// ---------------- small-table layer-1 contributions (qpu / time) -----------------
__global__ void k_contrib(const float* __restrict__ qpu_emb, const float* __restrict__ time_tab) {
    __shared__ float e_s[8 * H];
    int b = blockIdx.x, t = threadIdx.x;
    const float* E; const float* WT; float* out; int base;
    if (b < 8) { E = qpu_emb; WT = g_W1bT_map; out = g_qpu_contrib; base = b * 8; }
    else       { E = time_tab; WT = g_W1bT_sch; out = g_time_contrib; base = (b - 8) * 8; }
#pragma unroll
    for (int i = 0; i < 8; i++) e_s[i * H + t] = E[(size_t)(base + i) * H + t];
    __syncthreads();
    float acc[8];
#pragma unroll
    for (int i = 0; i < 8; i++) acc[i] = 0.0f;
    for (int k = 0; k < H; k++) {
        float w = WT[(size_t)k * H + t];
#pragma unroll
        for (int i = 0; i < 8; i++) acc[i] += e_s[i * H + k] * w;
    }
#pragma unroll
    for (int i = 0; i < 8; i++) out[(size_t)(base + i) * H + t] = acc[i];
}

// ---------------- query MLP + fold attention Q/K into U, c -----------------------
__global__ void k_small(const float* __restrict__ qgW1, const float* __restrict__ qgb1,
                        const float* __restrict__ qgW2, const float* __restrict__ qgb2,
                        const float* __restrict__ Wq,   const float* __restrict__ bq,
                        const float* __restrict__ Wk,   const float* __restrict__ bk) {
    __shared__ float g_s[H], h_s[H], qy_s[H], q_s[H];
    int t = threadIdx.x;
    g_s[t] = g_gsum[t] * (1.0f / 131072.0f);
    __syncthreads();
    float acc = qgb1[t];
    for (int k = 0; k < H; k++) acc += g_s[k] * qgW1[t * H + k];
    h_s[t] = fmaxf(acc, 0.0f);
    __syncthreads();
    acc = qgb2[t];
    for (int k = 0; k < H; k++) acc += h_s[k] * qgW2[t * H + k];
    qy_s[t] = acc;
    __syncthreads();
    acc = bq[t];
    for (int k = 0; k < H; k++) acc += qy_s[k] * Wq[t * H + k];
    q_s[t] = acc;
    __syncthreads();
#pragma unroll
    for (int hh = 0; hh < NH; hh++) {
        float u = 0.0f;
        for (int d = 0; d < 64; d++) u += q_s[hh * 64 + d] * Wk[(hh * 64 + d) * H + t];
        g_U[hh * H + t] = u * 0.125f;  // 1/sqrt(64)
    }
    if (t < NH) {
        float c = 0.0f;
        for (int d = 0; d < 64; d++) c += q_s[t * 64 + d] * bk[t * 64 + d];
        g_c[t] = c * 0.125f;
    }
}

// ---------------- main fused kernel: gather -> MLP (FFMA2) -> keys + scores ------
// smem: A_s 64*256 | B_s 32*257 (reused as P_s) | M_s 256
#define SMEM_MAIN ((64 * 256 + 32 * 257 + 256) * 4)

__global__ __launch_bounds__(256, 2) void k_mlp_main(
    const float* __restrict__ qubit_emb, const float* __restrict__ gate_emb,
    const int* __restrict__ map_qubit, const int* __restrict__ map_qpu,
    const int* __restrict__ sched_gate, const int* __restrict__ sched_time,
    const float* __restrict__ map_b1, const float* __restrict__ map_b2,
    const float* __restrict__ sch_b1, const float* __restrict__ sch_b2)
{
    extern __shared__ float smem[];
    float* A_s = smem;                       // 64 x 256
    float* B_s = smem + 64 * 256;            // 32 x 256 (GEMM) / 32 x 257 (P_s)
    float* M_s = B_s + 32 * 257;             // 256
    __shared__ int idx1_s[64];
    __shared__ int idx2_s[64];

    int tid = threadIdx.x;
    int rowbase = blockIdx.x * 64;
    bool is_map = rowbase < A_MAP;
    int lr = is_map ? rowbase : rowbase - A_MAP;
    const float* emb = is_map ? qubit_emb : gate_emb;
    const int* idx1 = is_map ? map_qubit : sched_gate;
    const int* idx2 = is_map ? map_qpu : sched_time;
    const float* contrib = is_map ? g_qpu_contrib : g_time_contrib;
    const float* W1T = is_map ? g_W1aT_map : g_W1aT_sch;
    const float* W2T = is_map ? g_W2T_map : g_W2T_sch;
    const float* b1 = is_map ? map_b1 : sch_b1;
    const float* b2 = is_map ? map_b2 : sch_b2;

    if (tid < 64) { idx1_s[tid] = idx1[lr + tid]; idx2_s[tid] = idx2[lr + tid]; }
    __syncthreads();

    // gather X tile [64 x 256]
    {
        int c4 = tid & 63;
        int r0 = tid >> 6;
#pragma unroll
        for (int p = 0; p < 16; p++) {
            int r = p * 4 + r0;
            const float4* src = (const float4*)(emb + (size_t)idx1_s[r] * H);
            ((float4*)(A_s + r * H))[c4] = src[c4];
        }
    }

    const int tc = tid & 31, tr = tid >> 5;
    unsigned long long acc[32];  // packed f32x2 accumulators: 8 rows x 4 col-pairs

#define RUN_GEMM(WT_)                                                                   \
    do {                                                                                 \
        _Pragma("unroll")                                                                \
        for (int i = 0; i < 32; i++) acc[i] = 0ULL;                                      \
        for (int k0 = 0; k0 < H; k0 += 32) {                                             \
            __syncthreads();                                                             \
            const float4* src = (const float4*)((WT_) + (size_t)k0 * H);                 \
            _Pragma("unroll")                                                            \
            for (int u = 0; u < 8; u++) ((float4*)B_s)[u * 256 + tid] = src[u * 256 + tid]; \
            __syncthreads();                                                             \
            _Pragma("unroll")                                                            \
            for (int kk = 0; kk < 32; kk++) {                                            \
                const ulonglong2* bp = (const ulonglong2*)(B_s + kk * H + tc * 8);       \
                ulonglong2 b01 = bp[0];                                                  \
                ulonglong2 b23 = bp[1];                                                  \
                unsigned long long bb0 = b01.x, bb1 = b01.y, bb2 = b23.x, bb3 = b23.y;   \
                _Pragma("unroll")                                                        \
                for (int i = 0; i < 8; i++) {                                            \
                    float a = A_s[(tr * 8 + i) * H + k0 + kk];                           \
                    unsigned long long a2;                                               \
                    asm("mov.b64 %0, {%1, %1};" : "=l"(a2) : "r"(__float_as_uint(a)));   \
                    asm("fma.rn.f32x2 %0, %1, %2, %0;" : "+l"(acc[i*4+0]) : "l"(a2), "l"(bb0)); \
                    asm("fma.rn.f32x2 %0, %1, %2, %0;" : "+l"(acc[i*4+1]) : "l"(a2), "l"(bb1)); \
                    asm("fma.rn.f32x2 %0, %1, %2, %0;" : "+l"(acc[i*4+2]) : "l"(a2), "l"(bb2)); \
                    asm("fma.rn.f32x2 %0, %1, %2, %0;" : "+l"(acc[i*4+3]) : "l"(a2), "l"(bb3)); \
                }                                                                        \
            }                                                                            \
        }                                                                                \
    } while (0)

    // ---- layer 1 ----
    RUN_GEMM(W1T);

    float hvals[8][8];
    {
        float4 b1a = *(const float4*)(b1 + tc * 8);
        float4 b1b = *(const float4*)(b1 + tc * 8 + 4);
        float b1v[8] = {b1a.x, b1a.y, b1a.z, b1a.w, b1b.x, b1b.y, b1b.z, b1b.w};
#pragma unroll
        for (int i = 0; i < 8; i++) {
            int r = tr * 8 + i;
            const float4* cp = (const float4*)(contrib + (size_t)idx2_s[r] * H + tc * 8);
            float4 ca = cp[0], cb = cp[1];
            float cv[8] = {ca.x, ca.y, ca.z, ca.w, cb.x, cb.y, cb.z, cb.w};
#pragma unroll
            for (int j = 0; j < 4; j++) {
                unsigned lo, hi;
                asm("mov.b64 {%0, %1}, %2;" : "=r"(lo), "=r"(hi) : "l"(acc[i * 4 + j]));
                hvals[i][2 * j]     = fmaxf(__uint_as_float(lo) + cv[2 * j]     + b1v[2 * j],     0.0f);
                hvals[i][2 * j + 1] = fmaxf(__uint_as_float(hi) + cv[2 * j + 1] + b1v[2 * j + 1], 0.0f);
            }
        }
    }
    __syncthreads();  // all warps done reading A_s (layer-1 inputs)
#pragma unroll
    for (int i = 0; i < 8; i++)
#pragma unroll
        for (int j = 0; j < 8; j++)
            A_s[(tr * 8 + i) * H + tc * 8 + j] = hvals[i][j];

    // ---- layer 2 ----
    RUN_GEMM(W2T);

    {
        float4 b2a = *(const float4*)(b2 + tc * 8);
        float4 b2b = *(const float4*)(b2 + tc * 8 + 4);
        float b2v[8] = {b2a.x, b2a.y, b2a.z, b2a.w, b2b.x, b2b.y, b2b.z, b2b.w};
        float Uv[NH][8];
#pragma unroll
        for (int hh = 0; hh < NH; hh++) {
            float4 ua = *(const float4*)(g_U + hh * H + tc * 8);
            float4 ub = *(const float4*)(g_U + hh * H + tc * 8 + 4);
            Uv[hh][0] = ua.x; Uv[hh][1] = ua.y; Uv[hh][2] = ua.z; Uv[hh][3] = ua.w;
            Uv[hh][4] = ub.x; Uv[hh][5] = ub.y; Uv[hh][6] = ub.z; Uv[hh][7] = ub.w;
        }
        __syncthreads();  // B_s free -> becomes P_s
        float* P_s = B_s; // [32][257] padded
#pragma unroll
        for (int i = 0; i < 8; i++) {
            int r = tr * 8 + i;
            float kv[8];
#pragma unroll
            for (int j = 0; j < 4; j++) {
                unsigned lo, hi;
                asm("mov.b64 {%0, %1}, %2;" : "=r"(lo), "=r"(hi) : "l"(acc[i * 4 + j]));
                kv[2 * j]     = __uint_as_float(lo) + b2v[2 * j];
                kv[2 * j + 1] = __uint_as_float(hi) + b2v[2 * j + 1];
            }
            float4* dst = (float4*)(g_keys + (size_t)(rowbase + r) * H + tc * 8);
            dst[0] = make_float4(kv[0], kv[1], kv[2], kv[3]);
            dst[1] = make_float4(kv[4], kv[5], kv[6], kv[7]);
            float sp0 = 0, sp1 = 0, sp2 = 0, sp3 = 0;
#pragma unroll
            for (int j = 0; j < 8; j++) {
                sp0 += kv[j] * Uv[0][j];
                sp1 += kv[j] * Uv[1][j];
                sp2 += kv[j] * Uv[2][j];
                sp3 += kv[j] * Uv[3][j];
            }
            P_s[tc * 257 + r * 4 + 0] = sp0;
            P_s[tc * 257 + r * 4 + 1] = sp1;
            P_s[tc * 257 + r * 4 + 2] = sp2;
            P_s[tc * 257 + r * 4 + 3] = sp3;
        }
        __syncthreads();
        // reduce partials across the 32 tc lanes: thread tid owns (row, head) = (tid>>2, tid&3)
        {
            float s = 0.0f;
#pragma unroll
            for (int t2 = 0; t2 < 32; t2++) s += P_s[t2 * 257 + tid];
            int hh = tid & 3, r = tid >> 2;
            s += g_c[hh];
            g_scores[(size_t)hh * A_TOT + rowbase + r] = s;
            M_s[hh * 64 + r] = s;
        }
        __syncthreads();
        if (tid < NH) {
            float m = -3.4e38f;
            for (int r = 0; r < 64; r++) m = fmaxf(m, M_s[tid * 64 + r]);
            atomicMax(&g_smax[tid], f2ord(m));
        }
    }
#undef RUN_GEMM
}

// ---------------- pass 2: softmax weights, weighted key-sum (cvec), expsum -------
__global__ void k_attn_acc() {
    __shared__ float w_s[NH * 256];
    __shared__ float red_s[NH * 8];
    int tid = threadIdx.x;
    size_t base = (size_t)blockIdx.x * 256;
    float sm[NH];
#pragma unroll
    for (int hh = 0; hh < NH; hh++) sm[hh] = ord2f(g_smax[hh]);
    float es[NH];
#pragma unroll
    for (int hh = 0; hh < NH; hh++) {
        float s = g_scores[(size_t)hh * A_TOT + base + tid];
        float w = __expf(s - sm[hh]);
        w_s[hh * 256 + tid] = w;
        es[hh] = w;
    }
    __syncthreads();
    float cv0 = 0, cv1 = 0, cv2 = 0, cv3 = 0;
    for (int r = 0; r < 256; r++) {
        float kj = g_keys[(base + r) * H + tid];
        cv0 += w_s[r] * kj;
        cv1 += w_s[256 + r] * kj;
        cv2 += w_s[512 + r] * kj;
        cv3 += w_s[768 + r] * kj;
    }
    atomicAdd(&g_cvec[0 * H + tid], cv0);
    atomicAdd(&g_cvec[1 * H + tid], cv1);
    atomicAdd(&g_cvec[2 * H + tid], cv2);
    atomicAdd(&g_cvec[3 * H + tid], cv3);
#pragma unroll
    for (int hh = 0; hh < NH; hh++)
        for (int off = 16; off; off >>= 1) es[hh] += __shfl_down_sync(0xffffffffu, es[hh], off);
    if ((tid & 31) == 0) {
        int w = tid >> 5;
#pragma unroll
        for (int hh = 0; hh < NH; hh++) red_s[hh * 8 + w] = es[hh];
    }
    __syncthreads();
    if (tid < NH) {
        float s = 0.0f;
#pragma unroll
        for (int w = 0; w < 8; w++) s += red_s[tid * 8 + w];
        atomicAdd(&g_expsum[tid], s);
    }
}

// ---------------- ctx -> attn_out ------------------------------------------------
__global__ void k_ctx(const float* __restrict__ Wv, const float* __restrict__ bv,
                      const float* __restrict__ Wo, const float* __restrict__ bo) {
    __shared__ float ctx_s[H];
    int t = threadIdx.x;
    int hh = t >> 6;
    float inv = 1.0f / g_expsum[hh];
    float acc = 0.0f;
    for (int j = 0; j < H; j++) acc += Wv[t * H + j] * g_cvec[hh * H + j];
    ctx_s[t] = acc * inv + bv[t];
    __syncthreads();
    float o = bo[t];
    for (int j = 0; j < H; j++) o += Wo[t * H + j] * ctx_s[j];
    g_attn_out[t] = o;
}

// ---------------- logits = keys @ attn_out, track max ----------------------------
__global__ void k_logits() {
    __shared__ float ao_s[H];
    __shared__ float m_s[64];
    int tid = threadIdx.x;
    ao_s[tid] = g_attn_out[tid];
    __syncthreads();
    int r = tid >> 2, q4 = tid & 3;
    size_t a = (size_t)blockIdx.x * 64 + r;
    const float4* kp = (const float4*)(g_keys + a * H + q4 * 64);
    const float4* ap = (const float4*)(ao_s + q4 * 64);
    float p = 0.0f;
#pragma unroll
    for (int u = 0; u < 16; u++) {
        float4 kv = kp[u];
        float4 av = ap[u];
        p += kv.x * av.x + kv.y * av.y + kv.z * av.z + kv.w * av.w;
    }
    p += __shfl_down_sync(0xffffffffu, p, 2);
    p += __shfl_down_sync(0xffffffffu, p, 1);
    if (q4 == 0) { g_logits[a] = p; m_s[r] = p; }
    __syncthreads();
    if (tid < 32) {
        float m = fmaxf(m_s[tid], m_s[tid + 32]);
        for (int off = 16; off; off >>= 1) m = fmaxf(m, __shfl_down_sync(0xffffffffu, m, off));
        if (tid == 0) atomicMax(&g_lmax, f2ord(m));
    }
}

// ---------------- softmax denominator over logits --------------------------------
__global__ void k_lsum() {
    __shared__ float r_s[256];
    float lmax = ord2f(g_lmax);
    float s = 0.0f;
    for (int i = blockIdx.x * 256 + threadIdx.x; i < A_TOT; i += 256 * 256)
        s += __expf(g_logits[i] - lmax);
    r_s[threadIdx.x] = s;
    __syncthreads();
    for (int off = 128; off; off >>= 1) {
        if (threadIdx.x < off) r_s[threadIdx.x] += r_s[threadIdx.x + off];
        __syncthreads();
    }
    if (threadIdx.x == 0) atomicAdd(&g_lsum, r_s[0]);
}

// ---------------- write probs (+ logits) to output -------------------------------
__global__ void k_probs(float* __restrict__ out, int write_logits) {
    int i = blockIdx.x * 256 + threadIdx.x;
    float lmax = ord2f(g_lmax);
    float l = g_logits[i];
    out[i] = __expf(l - lmax) / g_lsum;
    if (write_logits) out[A_TOT + i] = l;
}

// ---------------- launch ----------------------------------------------------------
extern "C" void kernel_launch(void* const* d_in, const int* in_sizes, int n_in,
                              void* d_out, int out_size) {
    const float* qubit_emb = (const float*)d_in[0];
    const float* qpu_emb   = (const float*)d_in[1];
    const float* gate_emb  = (const float*)d_in[2];
    const float* all_emb   = (const float*)d_in[3];
    const float* time_tab  = (const float*)d_in[4];
    const float* map_W1 = (const float*)d_in[5];
    const float* map_b1 = (const float*)d_in[6];
    const float* map_W2 = (const float*)d_in[7];
    const float* map_b2 = (const float*)d_in[8];
    const float* sch_W1 = (const float*)d_in[9];
    const float* sch_b1 = (const float*)d_in[10];
    const float* sch_W2 = (const float*)d_in[11];
    const float* sch_b2 = (const float*)d_in[12];
    const float* qg_W1 = (const float*)d_in[13];
    const float* qg_b1 = (const float*)d_in[14];
    const float* qg_W2 = (const float*)d_in[15];
    const float* qg_b2 = (const float*)d_in[16];
    const float* attn_Wq = (const float*)d_in[17];
    const float* attn_bq = (const float*)d_in[18];
    const float* attn_Wk = (const float*)d_in[19];
    const float* attn_bk = (const float*)d_in[20];
    const float* attn_Wv = (const float*)d_in[21];
    const float* attn_bv = (const float*)d_in[22];
    const float* attn_Wo = (const float*)d_in[23];
    const float* attn_bo = (const float*)d_in[24];
    const int* map_qubit  = (const int*)d_in[25];
    const int* map_qpu    = (const int*)d_in[26];
    const int* sched_gate = (const int*)d_in[27];
    const int* sched_time = (const int*)d_in[28];
    float* out = (float*)d_out;
    int write_logits = (out_size >= 2 * A_TOT) ? 1 : 0;

    cudaFuncSetAttribute(k_mlp_main, cudaFuncAttributeMaxDynamicSharedMemorySize, SMEM_MAIN);

    k_init<<<1, 1024>>>();
    k_transpose<<<dim3(64, 6), dim3(32, 8)>>>(map_W1, sch_W1, map_W2, sch_W2);
    k_mean<<<512, 256>>>(all_emb);
    k_contrib<<<133, 256>>>(qpu_emb, time_tab);
    k_small<<<1, 256>>>(qg_W1, qg_b1, qg_W2, qg_b2, attn_Wq, attn_bq, attn_Wk, attn_bk);
    k_mlp_main<<<4096, 256, SMEM_MAIN>>>(qubit_emb, gate_emb, map_qubit, map_qpu,
                                         sched_gate, sched_time,
                                         map_b1, map_b2, sch_b1, sch_b2);
    k_attn_acc<<<1024, 256>>>();
    k_ctx<<<1, 256>>>(attn_Wv, attn_bv, attn_Wo, attn_bo);
    k_logits<<<4096, 256>>>();
    k_lsum<<<256, 256>>>();
    k_probs<<<1024, 256>>>(out, write_logits);
}

// round 4
// speedup vs baseline: 1.0538x; 1.0538x over previous
#include <cuda_runtime.h>
#include <math.h>

#define H 256
#define A_TOT 262144
#define A_MAP 131072
#define NH 4

// ---------------- scratch (device globals; no allocation allowed) ----------------
__device__ float g_keys[(size_t)A_TOT * H];          // 256 MB
__device__ float g_scores[NH * A_TOT];               // 4 MB
__device__ float g_logits[A_TOT];                    // 1 MB
__device__ float g_W1aT_map[H * H];
__device__ float g_W1aT_sch[H * H];
__device__ float g_W1bT_map[H * H];
__device__ float g_W1bT_sch[H * H];
__device__ float g_W2T_map[H * H];
__device__ float g_W2T_sch[H * H];
__device__ float g_qpu_contrib[64 * H];
__device__ float g_time_contrib[1000 * H];
__device__ float g_gsum[H];
__device__ float g_U[NH * H];
__device__ float g_c[NH];
__device__ float g_attn_out[H];
__device__ float g_cvec[NH * H];
__device__ float g_expsum[NH];
__device__ unsigned g_smax[NH];
__device__ unsigned g_lmax;
__device__ float g_lsum;

// ordered-uint encoding for fp32 atomic max
__device__ __forceinline__ unsigned f2ord(float f) {
    unsigned u = __float_as_uint(f);
    return (u & 0x80000000u) ? ~u : (u | 0x80000000u);
}
__device__ __forceinline__ float ord2f(unsigned u) {
    u = (u & 0x80000000u) ? (u ^ 0x80000000u) : ~u;
    return __uint_as_float(u);
}

// ---------------- init (reset accumulators every launch; graph-replay safe) ------
__global__ void k_init() {
    int t = threadIdx.x;
    if (t < H) g_gsum[t] = 0.0f;
    if (t < NH * H) g_cvec[t] = 0.0f;
    if (t < NH) { g_expsum[t] = 0.0f; g_smax[t] = 0x007FFFFFu; /* f2ord(-inf) */ }
    if (t == 0) { g_lsum = 0.0f; g_lmax = 0x007FFFFFu; }
}

// ---------------- transpose the weight matrices we stream as B operands ----------
__global__ void k_transpose(const float* __restrict__ mapW1, const float* __restrict__ schW1,
                            const float* __restrict__ mapW2, const float* __restrict__ schW2) {
    __shared__ float s[32][33];
    const float* src; float* dst; int ld, off;
    switch (blockIdx.y) {
        case 0: src = mapW1; ld = 512; off = 0;   dst = g_W1aT_map; break;
        case 1: src = mapW1; ld = 512; off = 256; dst = g_W1bT_map; break;
        case 2: src = schW1; ld = 512; off = 0;   dst = g_W1aT_sch; break;
        case 3: src = schW1; ld = 512; off = 256; dst = g_W1bT_sch; break;
        case 4: src = mapW2; ld = 256; off = 0;   dst = g_W2T_map;  break;
        default: src = schW2; ld = 256; off = 0;  dst = g_W2T_sch;  break;
    }
    int k0 = (blockIdx.x & 7) * 32;
    int n0 = (blockIdx.x >> 3) * 32;
    int tx = threadIdx.x, ty = threadIdx.y;  // 32 x 8
#pragma unroll
    for (int i = 0; i < 32; i += 8)
        s[ty + i][tx] = src[(size_t)(n0 + ty + i) * ld + off + k0 + tx];
    __syncthreads();
#pragma unroll
    for (int i = 0; i < 32; i += 8)
        dst[(size_t)(k0 + ty + i) * H + n0 + tx] = s[tx][ty + i];
}

// ---------------- g = mean(all_embeddings) ---------------------------------------
__global__ void k_mean(const float* __restrict__ all_emb) {
    int t = threadIdx.x;
    size_t base = (size_t)blockIdx.x * 256;
    float s = 0.0f;
    for (int r = 0; r < 256; r++) s += all_emb[(base + r) * H + t];
    atomicAdd(&g_gsum[t], s);
}

// ---------------- small-table layer-1 contributions (qpu / time) -----------------
__global__ void k_contrib(const float* __restrict__ qpu_emb, const float* __restrict__ time_tab) {
    __shared__ float e_s[8 * H];
    int b = blockIdx.x, t = threadIdx.x;
    const float* E; const float* WT; float* out; int base;
    if (b < 8) { E = qpu_emb; WT = g_W1bT_map; out = g_qpu_contrib; base = b * 8; }
    else       { E = time_tab; WT = g_W1bT_sch; out = g_time_contrib; base = (b - 8) * 8; }
#pragma unroll
    for (int i = 0; i < 8; i++) e_s[i * H + t] = E[(size_t)(base + i) * H + t];
    __syncthreads();
    float acc[8];
#pragma unroll
    for (int i = 0; i < 8; i++) acc[i] = 0.0f;
    for (int k = 0; k < H; k++) {
        float w = WT[(size_t)k * H + t];
#pragma unroll
        for (int i = 0; i < 8; i++) acc[i] += e_s[i * H + k] * w;
    }
#pragma unroll
    for (int i = 0; i < 8; i++) out[(size_t)(base + i) * H + t] = acc[i];
}

// ---------------- query MLP + fold attention Q/K into U, c -----------------------
__global__ void k_small(const float* __restrict__ qgW1, const float* __restrict__ qgb1,
                        const float* __restrict__ qgW2, const float* __restrict__ qgb2,
                        const float* __restrict__ Wq,   const float* __restrict__ bq,
                        const float* __restrict__ Wk,   const float* __restrict__ bk) {
    __shared__ float g_s[H], h_s[H], qy_s[H], q_s[H];
    int t = threadIdx.x;
    g_s[t] = g_gsum[t] * (1.0f / 131072.0f);
    __syncthreads();
    float acc = qgb1[t];
    for (int k = 0; k < H; k++) acc += g_s[k] * qgW1[t * H + k];
    h_s[t] = fmaxf(acc, 0.0f);
    __syncthreads();
    acc = qgb2[t];
    for (int k = 0; k < H; k++) acc += h_s[k] * qgW2[t * H + k];
    qy_s[t] = acc;
    __syncthreads();
    acc = bq[t];
    for (int k = 0; k < H; k++) acc += qy_s[k] * Wq[t * H + k];
    q_s[t] = acc;
    __syncthreads();
#pragma unroll
    for (int hh = 0; hh < NH; hh++) {
        float u = 0.0f;
        for (int d = 0; d < 64; d++) u += q_s[hh * 64 + d] * Wk[(hh * 64 + d) * H + t];
        g_U[hh * H + t] = u * 0.125f;  // 1/sqrt(64)
    }
    if (t < NH) {
        float c = 0.0f;
        for (int d = 0; d < 64; d++) c += q_s[t * 64 + d] * bk[t * 64 + d];
        g_c[t] = c * 0.125f;
    }
}

// ---------------- main fused kernel: gather -> MLP (FFMA2) -> keys + scores ------
// smem: A_s 64*256 | B_s 32*257 (reused as P_s) | M_s 256
#define SMEM_MAIN ((64 * 256 + 32 * 257 + 256) * 4)

__global__ __launch_bounds__(256, 2) void k_mlp_main(
    const float* __restrict__ qubit_emb, const float* __restrict__ gate_emb,
    const int* __restrict__ map_qubit, const int* __restrict__ map_qpu,
    const int* __restrict__ sched_gate, const int* __restrict__ sched_time,
    const float* __restrict__ map_b1, const float* __restrict__ map_b2,
    const float* __restrict__ sch_b1, const float* __restrict__ sch_b2)
{
    extern __shared__ float smem[];
    float* A_s = smem;                       // 64 x 256
    float* B_s = smem + 64 * 256;            // 32 x 256 (GEMM) / 32 x 257 (P_s)
    float* M_s = B_s + 32 * 257;             // 256
    __shared__ int idx1_s[64];
    __shared__ int idx2_s[64];

    int tid = threadIdx.x;
    int rowbase = blockIdx.x * 64;
    bool is_map = rowbase < A_MAP;
    int lr = is_map ? rowbase : rowbase - A_MAP;
    const float* emb = is_map ? qubit_emb : gate_emb;
    const int* idx1 = is_map ? map_qubit : sched_gate;
    const int* idx2 = is_map ? map_qpu : sched_time;
    const float* contrib = is_map ? g_qpu_contrib : g_time_contrib;
    const float* W1T = is_map ? g_W1aT_map : g_W1aT_sch;
    const float* W2T = is_map ? g_W2T_map : g_W2T_sch;
    const float* b1 = is_map ? map_b1 : sch_b1;
    const float* b2 = is_map ? map_b2 : sch_b2;

    if (tid < 64) { idx1_s[tid] = idx1[lr + tid]; idx2_s[tid] = idx2[lr + tid]; }
    __syncthreads();

    // gather X tile [64 x 256]
    {
        int c4 = tid & 63;
        int r0 = tid >> 6;
#pragma unroll
        for (int p = 0; p < 16; p++) {
            int r = p * 4 + r0;
            const float4* src = (const float4*)(emb + (size_t)idx1_s[r] * H);
            ((float4*)(A_s + r * H))[c4] = src[c4];
        }
    }

    const int tc = tid & 31, tr = tid >> 5;
    unsigned long long acc[32];  // packed f32x2 accumulators: 8 rows x 4 col-pairs

#define RUN_GEMM(WT_)                                                                   \
    do {                                                                                 \
        _Pragma("unroll")                                                                \
        for (int i = 0; i < 32; i++) acc[i] = 0ULL;                                      \
        for (int k0 = 0; k0 < H; k0 += 32) {                                             \
            __syncthreads();                                                             \
            const float4* src = (const float4*)((WT_) + (size_t)k0 * H);                 \
            _Pragma("unroll")                                                            \
            for (int u = 0; u < 8; u++) ((float4*)B_s)[u * 256 + tid] = src[u * 256 + tid]; \
            __syncthreads();                                                             \
            _Pragma("unroll")                                                            \
            for (int kk = 0; kk < 32; kk++) {                                            \
                const ulonglong2* bp = (const ulonglong2*)(B_s + kk * H + tc * 8);       \
                ulonglong2 b01 = bp[0];                                                  \
                ulonglong2 b23 = bp[1];                                                  \
                unsigned long long bb0 = b01.x, bb1 = b01.y, bb2 = b23.x, bb3 = b23.y;   \
                _Pragma("unroll")                                                        \
                for (int i = 0; i < 8; i++) {                                            \
                    float a = A_s[(tr * 8 + i) * H + k0 + kk];                           \
                    unsigned long long a2;                                               \
                    asm("mov.b64 %0, {%1, %1};" : "=l"(a2) : "r"(__float_as_uint(a)));   \
                    asm("fma.rn.f32x2 %0, %1, %2, %0;" : "+l"(acc[i*4+0]) : "l"(a2), "l"(bb0)); \
                    asm("fma.rn.f32x2 %0, %1, %2, %0;" : "+l"(acc[i*4+1]) : "l"(a2), "l"(bb1)); \
                    asm("fma.rn.f32x2 %0, %1, %2, %0;" : "+l"(acc[i*4+2]) : "l"(a2), "l"(bb2)); \
                    asm("fma.rn.f32x2 %0, %1, %2, %0;" : "+l"(acc[i*4+3]) : "l"(a2), "l"(bb3)); \
                }                                                                        \
            }                                                                            \
        }                                                                                \
    } while (0)

    // ---- layer 1 ----
    RUN_GEMM(W1T);

    float hvals[8][8];
    {
        float4 b1a = *(const float4*)(b1 + tc * 8);
        float4 b1b = *(const float4*)(b1 + tc * 8 + 4);
        float b1v[8] = {b1a.x, b1a.y, b1a.z, b1a.w, b1b.x, b1b.y, b1b.z, b1b.w};
#pragma unroll
        for (int i = 0; i < 8; i++) {
            int r = tr * 8 + i;
            const float4* cp = (const float4*)(contrib + (size_t)idx2_s[r] * H + tc * 8);
            float4 ca = cp[0], cb = cp[1];
            float cv[8] = {ca.x, ca.y, ca.z, ca.w, cb.x, cb.y, cb.z, cb.w};
#pragma unroll
            for (int j = 0; j < 4; j++) {
                unsigned lo, hi;
                asm("mov.b64 {%0, %1}, %2;" : "=r"(lo), "=r"(hi) : "l"(acc[i * 4 + j]));
                hvals[i][2 * j]     = fmaxf(__uint_as_float(lo) + cv[2 * j]     + b1v[2 * j],     0.0f);
                hvals[i][2 * j + 1] = fmaxf(__uint_as_float(hi) + cv[2 * j + 1] + b1v[2 * j + 1], 0.0f);
            }
        }
    }
    __syncthreads();  // all warps done reading A_s (layer-1 inputs)
#pragma unroll
    for (int i = 0; i < 8; i++)
#pragma unroll
        for (int j = 0; j < 8; j++)
            A_s[(tr * 8 + i) * H + tc * 8 + j] = hvals[i][j];

    // ---- layer 2 ----
    RUN_GEMM(W2T);

    {
        float4 b2a = *(const float4*)(b2 + tc * 8);
        float4 b2b = *(const float4*)(b2 + tc * 8 + 4);
        float b2v[8] = {b2a.x, b2a.y, b2a.z, b2a.w, b2b.x, b2b.y, b2b.z, b2b.w};
        float Uv[NH][8];
#pragma unroll
        for (int hh = 0; hh < NH; hh++) {
            float4 ua = *(const float4*)(g_U + hh * H + tc * 8);
            float4 ub = *(const float4*)(g_U + hh * H + tc * 8 + 4);
            Uv[hh][0] = ua.x; Uv[hh][1] = ua.y; Uv[hh][2] = ua.z; Uv[hh][3] = ua.w;
            Uv[hh][4] = ub.x; Uv[hh][5] = ub.y; Uv[hh][6] = ub.z; Uv[hh][7] = ub.w;
        }
        __syncthreads();  // B_s free -> becomes P_s
        float* P_s = B_s; // [32][257] padded
#pragma unroll
        for (int i = 0; i < 8; i++) {
            int r = tr * 8 + i;
            float kv[8];
#pragma unroll
            for (int j = 0; j < 4; j++) {
                unsigned lo, hi;
                asm("mov.b64 {%0, %1}, %2;" : "=r"(lo), "=r"(hi) : "l"(acc[i * 4 + j]));
                kv[2 * j]     = __uint_as_float(lo) + b2v[2 * j];
                kv[2 * j + 1] = __uint_as_float(hi) + b2v[2 * j + 1];
            }
            float4* dst = (float4*)(g_keys + (size_t)(rowbase + r) * H + tc * 8);
            dst[0] = make_float4(kv[0], kv[1], kv[2], kv[3]);
            dst[1] = make_float4(kv[4], kv[5], kv[6], kv[7]);
            float sp0 = 0, sp1 = 0, sp2 = 0, sp3 = 0;
#pragma unroll
            for (int j = 0; j < 8; j++) {
                sp0 += kv[j] * Uv[0][j];
                sp1 += kv[j] * Uv[1][j];
                sp2 += kv[j] * Uv[2][j];
                sp3 += kv[j] * Uv[3][j];
            }
            P_s[tc * 257 + r * 4 + 0] = sp0;
            P_s[tc * 257 + r * 4 + 1] = sp1;
            P_s[tc * 257 + r * 4 + 2] = sp2;
            P_s[tc * 257 + r * 4 + 3] = sp3;
        }
        __syncthreads();
        // reduce partials across the 32 tc lanes: thread tid owns (row, head) = (tid>>2, tid&3)
        {
            float s = 0.0f;
#pragma unroll
            for (int t2 = 0; t2 < 32; t2++) s += P_s[t2 * 257 + tid];
            int hh = tid & 3, r = tid >> 2;
            s += g_c[hh];
            g_scores[(size_t)hh * A_TOT + rowbase + r] = s;
            M_s[hh * 64 + r] = s;
        }
        __syncthreads();
        if (tid < NH) {
            float m = -3.4e38f;
            for (int r = 0; r < 64; r++) m = fmaxf(m, M_s[tid * 64 + r]);
            atomicMax(&g_smax[tid], f2ord(m));
        }
    }
#undef RUN_GEMM
}

// ---------------- pass 2: softmax weights, weighted key-sum (cvec), expsum -------
__global__ void k_attn_acc() {
    __shared__ float w_s[NH * 256];
    __shared__ float red_s[NH * 8];
    int tid = threadIdx.x;
    size_t base = (size_t)blockIdx.x * 256;
    float sm[NH];
#pragma unroll
    for (int hh = 0; hh < NH; hh++) sm[hh] = ord2f(g_smax[hh]);
    float es[NH];
#pragma unroll
    for (int hh = 0; hh < NH; hh++) {
        float s = g_scores[(size_t)hh * A_TOT + base + tid];
        float w = __expf(s - sm[hh]);
        w_s[hh * 256 + tid] = w;
        es[hh] = w;
    }
    __syncthreads();
    float cv0 = 0, cv1 = 0, cv2 = 0, cv3 = 0;
    for (int r = 0; r < 256; r++) {
        float kj = g_keys[(base + r) * H + tid];
        cv0 += w_s[r] * kj;
        cv1 += w_s[256 + r] * kj;
        cv2 += w_s[512 + r] * kj;
        cv3 += w_s[768 + r] * kj;
    }
    atomicAdd(&g_cvec[0 * H + tid], cv0);
    atomicAdd(&g_cvec[1 * H + tid], cv1);
    atomicAdd(&g_cvec[2 * H + tid], cv2);
    atomicAdd(&g_cvec[3 * H + tid], cv3);
#pragma unroll
    for (int hh = 0; hh < NH; hh++)
        for (int off = 16; off; off >>= 1) es[hh] += __shfl_down_sync(0xffffffffu, es[hh], off);
    if ((tid & 31) == 0) {
        int w = tid >> 5;
#pragma unroll
        for (int hh = 0; hh < NH; hh++) red_s[hh * 8 + w] = es[hh];
    }
    __syncthreads();
    if (tid < NH) {
        float s = 0.0f;
#pragma unroll
        for (int w = 0; w < 8; w++) s += red_s[tid * 8 + w];
        atomicAdd(&g_expsum[tid], s);
    }
}

// ---------------- ctx -> attn_out ------------------------------------------------
__global__ void k_ctx(const float* __restrict__ Wv, const float* __restrict__ bv,
                      const float* __restrict__ Wo, const float* __restrict__ bo) {
    __shared__ float ctx_s[H];
    int t = threadIdx.x;
    int hh = t >> 6;
    float inv = 1.0f / g_expsum[hh];
    float acc = 0.0f;
    for (int j = 0; j < H; j++) acc += Wv[t * H + j] * g_cvec[hh * H + j];
    ctx_s[t] = acc * inv + bv[t];
    __syncthreads();
    float o = bo[t];
    for (int j = 0; j < H; j++) o += Wo[t * H + j] * ctx_s[j];
    g_attn_out[t] = o;
}

// ---------------- logits = keys @ attn_out, track max ----------------------------
__global__ void k_logits() {
    __shared__ float ao_s[H];
    __shared__ float m_s[64];
    int tid = threadIdx.x;
    ao_s[tid] = g_attn_out[tid];
    __syncthreads();
    int r = tid >> 2, q4 = tid & 3;
    size_t a = (size_t)blockIdx.x * 64 + r;
    const float4* kp = (const float4*)(g_keys + a * H + q4 * 64);
    const float4* ap = (const float4*)(ao_s + q4 * 64);
    float p = 0.0f;
#pragma unroll
    for (int u = 0; u < 16; u++) {
        float4 kv = kp[u];
        float4 av = ap[u];
        p += kv.x * av.x + kv.y * av.y + kv.z * av.z + kv.w * av.w;
    }
    p += __shfl_down_sync(0xffffffffu, p, 2);
    p += __shfl_down_sync(0xffffffffu, p, 1);
    if (q4 == 0) { g_logits[a] = p; m_s[r] = p; }
    __syncthreads();
    if (tid < 32) {
        float m = fmaxf(m_s[tid], m_s[tid + 32]);
        for (int off = 16; off; off >>= 1) m = fmaxf(m, __shfl_down_sync(0xffffffffu, m, off));
        if (tid == 0) atomicMax(&g_lmax, f2ord(m));
    }
}

// ---------------- softmax denominator over logits --------------------------------
__global__ void k_lsum() {
    __shared__ float r_s[256];
    float lmax = ord2f(g_lmax);
    float s = 0.0f;
    for (int i = blockIdx.x * 256 + threadIdx.x; i < A_TOT; i += 256 * 256)
        s += __expf(g_logits[i] - lmax);
    r_s[threadIdx.x] = s;
    __syncthreads();
    for (int off = 128; off; off >>= 1) {
        if (threadIdx.x < off) r_s[threadIdx.x] += r_s[threadIdx.x + off];
        __syncthreads();
    }
    if (threadIdx.x == 0) atomicAdd(&g_lsum, r_s[0]);
}

// ---------------- write probs (+ logits) to output -------------------------------
__global__ void k_probs(float* __restrict__ out, int write_logits) {
    int i = blockIdx.x * 256 + threadIdx.x;
    float lmax = ord2f(g_lmax);
    float l = g_logits[i];
    out[i] = __expf(l - lmax) / g_lsum;
    if (write_logits) out[A_TOT + i] = l;
}

// ---------------- launch ----------------------------------------------------------
extern "C" void kernel_launch(void* const* d_in, const int* in_sizes, int n_in,
                              void* d_out, int out_size) {
    const float* qubit_emb = (const float*)d_in[0];
    const float* qpu_emb   = (const float*)d_in[1];
    const float* gate_emb  = (const float*)d_in[2];
    const float* all_emb   = (const float*)d_in[3];
    const float* time_tab  = (const float*)d_in[4];
    const float* map_W1 = (const float*)d_in[5];
    const float* map_b1 = (const float*)d_in[6];
    const float* map_W2 = (const float*)d_in[7];
    const float* map_b2 = (const float*)d_in[8];
    const float* sch_W1 = (const float*)d_in[9];
    const float* sch_b1 = (const float*)d_in[10];
    const float* sch_W2 = (const float*)d_in[11];
    const float* sch_b2 = (const float*)d_in[12];
    const float* qg_W1 = (const float*)d_in[13];
    const float* qg_b1 = (const float*)d_in[14];
    const float* qg_W2 = (const float*)d_in[15];
    const float* qg_b2 = (const float*)d_in[16];
    const float* attn_Wq = (const float*)d_in[17];
    const float* attn_bq = (const float*)d_in[18];
    const float* attn_Wk = (const float*)d_in[19];
    const float* attn_bk = (const float*)d_in[20];
    const float* attn_Wv = (const float*)d_in[21];
    const float* attn_bv = (const float*)d_in[22];
    const float* attn_Wo = (const float*)d_in[23];
    const float* attn_bo = (const float*)d_in[24];
    const int* map_qubit  = (const int*)d_in[25];
    const int* map_qpu    = (const int*)d_in[26];
    const int* sched_gate = (const int*)d_in[27];
    const int* sched_time = (const int*)d_in[28];
    float* out = (float*)d_out;
    int write_logits = (out_size >= 2 * A_TOT) ? 1 : 0;

    cudaFuncSetAttribute(k_mlp_main, cudaFuncAttributeMaxDynamicSharedMemorySize, SMEM_MAIN);

    k_init<<<1, 1024>>>();
    k_transpose<<<dim3(64, 6), dim3(32, 8)>>>(map_W1, sch_W1, map_W2, sch_W2);
    k_mean<<<512, 256>>>(all_emb);
    k_contrib<<<133, 256>>>(qpu_emb, time_tab);
    k_small<<<1, 256>>>(qg_W1, qg_b1, qg_W2, qg_b2, attn_Wq, attn_bq, attn_Wk, attn_bk);
    k_mlp_main<<<4096, 256, SMEM_MAIN>>>(qubit_emb, gate_emb, map_qubit, map_qpu,
                                         sched_gate, sched_time,
                                         map_b1, map_b2, sch_b1, sch_b2);
    k_attn_acc<<<1024, 256>>>();
    k_ctx<<<1, 256>>>(attn_Wv, attn_bv, attn_Wo, attn_bo);
    k_logits<<<4096, 256>>>();
    k_lsum<<<256, 256>>>();
    k_probs<<<1024, 256>>>(out, write_logits);
}